// round 16
// baseline (speedup 1.0000x reference)
#include <cuda_runtime.h>
#include <math.h>
#include <stdint.h>

// MarginalGaussianization forward on GB300 — exact-fixup + warp-staged global I/O.
// Inputs: x [B,64] f32, x_values [64,1000] f32 (sorted linspace/row),
// cdf_values [64,1000] f32 (strictly increasing). Output: z [B,64] then log_det [B].
//
//  - 8 dim-groups x 18 chunks = 144 blocks (single wave on 148 SMs), TPB=1024.
//  - smem: payload float4[8][1000] (x_l, slope, c_l, x_r) = 128000 B
//          + per-warp x/z staging (2 planes of 32 float4 + 64B pad) 2x36864 B.
//  - Global I/O via cooperative pair-lane LDG/STG through staging: each warp
//    instr touches 16 lines -> 1 L1 wavefront per sample per direction
//    (vs 2+2 for direct thread-per-sample). Staging layout is bank-conflict
//    free for every STS/LDS (plane1 offset = 144 words = 16 mod 32).
//  - Hot path: 1-FMA bin guess + exact +/-1 fixup (searchsorted semantics,
//    rel_err ~1.6e-7), one LDS.128/dim, branch-lean Giles erfinv,
//    log-det term = __logf(slope) + log(sqrt(2pi)) + 0.5*z^2.

#define DIMS    64
#define NBK     1000
#define GROUPS  8
#define DPG     8
#define TPB     1024
#define NWARP   (TPB / 32)
#define NCHUNK  18
#define BMAX    262144

#define SMEM_TAB_BYTES  (DPG * NBK * 16)            // 128000
#define WSTAGE_FLOATS   288                          // plane0(128) + pad(16) + plane1(128) + pad(16)
#define PLANE1          144                          // float offset of plane1 (== 16 mod 32 banks)
#define SMEM_XS_OFF     SMEM_TAB_BYTES
#define SMEM_ZS_OFF     (SMEM_XS_OFF + NWARP * WSTAGE_FLOATS * 4)   // +36864
#define SMEM_TOTAL      (SMEM_ZS_OFF + NWARP * WSTAGE_FLOATS * 4)   // 201728

__device__ float g_partial[GROUPS * (size_t)BMAX];

// ---------------- shared table build ----------------
// payload ent[j] = (x_l, slope, c_l, x_r); dinfo = (inv_step, bias)
__device__ __forceinline__ void build_table(float4* tab, float2* dinfo_s,
                                            const float* __restrict__ xv,
                                            const float* __restrict__ cdf,
                                            int d0, int tid)
{
    for (int idx = tid; idx < DPG * (NBK - 1); idx += TPB) {
        int k = idx / (NBK - 1);
        int j = idx - k * (NBK - 1);
        const float* xvk = xv  + (size_t)(d0 + k) * NBK;
        const float* ck  = cdf + (size_t)(d0 + k) * NBK;
        float xl = xvk[j], xr = xvk[j + 1];
        float cl = ck[j],  cr = ck[j + 1];
        float denom = xr - xl + 1e-12f;
        float s = (cr - cl) / denom;                          // matches reference math
        tab[k * NBK + j] = make_float4(xl, s, cl, xr);
    }
    if (tid < DPG) {
        const float* xvk = xv + (size_t)(d0 + tid) * NBK;
        float x0 = xvk[0], x1 = xvk[NBK - 1];
        float inv = (float)(NBK - 1) / (x1 - x0);
        dinfo_s[tid] = make_float2(inv, -x0 * inv);           // j_guess = fma(x, inv, bias)
    }
}

// ---------------- per-element hot path (exact searchsorted semantics) ----------------
__device__ __forceinline__ float gauss_term(float xk, float2 dik, const float4* tk, float& zz)
{
    // analytic bin guess on the linspace grid (provably within +/-1 of truth)
    int j = __float2int_rd(fmaf(xk, dik.x, dik.y));
    j = max(0, min(j, NBK - 2));

    float4 e = tk[j];                                         // (x_l, slope, c_l, x_r)

    // exact +/-1 fixup; reload only if some lane moved (rare per warp)
    int j2 = j + (int)(xk > e.w) - (int)(xk <= e.x);
    j2 = max(0, min(j2, NBK - 2));
    if (__any_sync(0xffffffffu, j2 != j)) {
        if (j2 != j) e = tk[j2];
    }

    // u = c_l + slope*(x - x_l); t-clamp subsumes the reference's u-clip
    float u = fmaf(e.y, xk - e.x, e.z);
    float tt = fmaf(2.0f, u, -1.0f);
    tt = fminf(fmaxf(tt, -0.99999f), 0.99999f);

    // erfinv (Giles): central poly always; tail only if some lane needs it
    float w  = -__logf(fmaf(tt, -tt, 1.0f));                  // w in (0, ~10.82]
    float wc = w - 2.5f;

    float p =               2.81022636e-08f;
    p = fmaf(p, wc,         3.43273939e-07f);
    p = fmaf(p, wc,        -3.5233877e-06f);
    p = fmaf(p, wc,        -4.39150654e-06f);
    p = fmaf(p, wc,         0.00021858087f);
    p = fmaf(p, wc,        -0.00125372503f);
    p = fmaf(p, wc,        -0.00417768164f);
    p = fmaf(p, wc,         0.246640727f);
    p = fmaf(p, wc,         1.50140941f);

    if (__any_sync(0xffffffffu, w >= 5.0f)) {
        float wt = sqrtf(w) - 3.0f;
        float pt =              -0.000200214257f;
        pt = fmaf(pt, wt,        0.000100950558f);
        pt = fmaf(pt, wt,        0.00134934322f);
        pt = fmaf(pt, wt,       -0.00367342844f);
        pt = fmaf(pt, wt,        0.00573950773f);
        pt = fmaf(pt, wt,       -0.0076224613f);
        pt = fmaf(pt, wt,        0.00943887047f);
        pt = fmaf(pt, wt,        1.00167406f);
        pt = fmaf(pt, wt,        2.83297682f);
        p = (w < 5.0f) ? p : pt;
    }

    zz = 1.4142135623730951f * p * tt;                        // |z| <= 4.42 < 10: no clip

    // term = log(p_hat) - log(phi + 1e-12)
    //      = log(max(slope,1e-12)) + log(sqrt(2pi)) + 0.5*z^2   (err < 5e-8)
    float L = __logf(fmaxf(e.y, 1e-12f)) + 0.91893853320467274f;
    return fmaf(0.5f * zz, zz, L);
}

// ---------------- main kernel ----------------
__global__ __launch_bounds__(TPB)
void mg_main(const float* __restrict__ x,
             const float* __restrict__ xv,
             const float* __restrict__ cdf,
             float* __restrict__ zout,
             int B, int spb)
{
    extern __shared__ char smem_raw[];
    float4* tab = (float4*)smem_raw;                          // [DPG][NBK]
    __shared__ float2 dinfo_s[DPG];

    const int tid  = threadIdx.x;
    const int lane = tid & 31;
    const int wid  = tid >> 5;
    const int g    = blockIdx.y;
    const int d0   = g * DPG;

    build_table(tab, dinfo_s, xv, cdf, d0, tid);
    __syncthreads();

    float2 di[DPG];
    #pragma unroll
    for (int k = 0; k < DPG; k++) di[k] = dinfo_s[k];

    float* xsw = (float*)(smem_raw + SMEM_XS_OFF) + wid * WSTAGE_FLOATS;
    float* zsw = (float*)(smem_raw + SMEM_ZS_OFF) + wid * WSTAGE_FLOATS;

    const int b0   = blockIdx.x * spb;
    const int bend = min(B, b0 + spb);
    const int half = (lane & 1) * 4;                          // 16B chunk in a 32B slice
    const int hs   = lane >> 1;                               // sample-half index 0..15
    const int coff = (lane & 1) * PLANE1;                     // staging plane offset

    const int niter = (spb + TPB - 1) / TPB;

    for (int m = 0; m < niter; m++) {
        const int sw = b0 + m * TPB + wid * 32;               // warp's 32-sample base
        if (sw >= bend) break;                                // warp-uniform

        const int sA = sw + hs;                               // cooperative samples
        const int sB = sA + 16;

        // ---- cooperative x load: 16 lines/instr -> 1 wf/sample ----
        if (sA < bend)
            ((float4*)(xsw + coff))[hs] =
                *(const float4*)(x + (size_t)sA * DIMS + d0 + half);
        if (sB < bend)
            ((float4*)(xsw + coff))[hs + 16] =
                *(const float4*)(x + (size_t)sB * DIMS + d0 + half);
        __syncwarp();

        // ---- compute: thread-per-sample from conflict-free staging ----
        const int s = sw + lane;
        float4 xa = ((const float4*)xsw)[lane];               // dims 0-3
        float4 xb = ((const float4*)(xsw + PLANE1))[lane];    // dims 4-7

        float acc;
        float4 z0, z1;
        acc  = gauss_term(xa.x, di[0], tab + 0 * NBK, z0.x);
        acc += gauss_term(xa.y, di[1], tab + 1 * NBK, z0.y);
        acc += gauss_term(xa.z, di[2], tab + 2 * NBK, z0.z);
        acc += gauss_term(xa.w, di[3], tab + 3 * NBK, z0.w);
        acc += gauss_term(xb.x, di[4], tab + 4 * NBK, z1.x);
        acc += gauss_term(xb.y, di[5], tab + 5 * NBK, z1.y);
        acc += gauss_term(xb.z, di[6], tab + 6 * NBK, z1.z);
        acc += gauss_term(xb.w, di[7], tab + 7 * NBK, z1.w);

        ((float4*)zsw)[lane] = z0;
        ((float4*)(zsw + PLANE1))[lane] = z1;
        if (s < bend) g_partial[(size_t)g * B + s] = acc;     // coalesced
        __syncwarp();

        // ---- cooperative z store: 16 lines/instr -> 1 wf/sample ----
        float4 v0 = ((const float4*)(zsw + coff))[hs];
        if (sA < bend)
            *(float4*)(zout + (size_t)sA * DIMS + d0 + half) = v0;
        float4 v1 = ((const float4*)(zsw + coff))[hs + 16];
        if (sB < bend)
            *(float4*)(zout + (size_t)sB * DIMS + d0 + half) = v1;
        // next iteration's x-STS is ordered after this by its own __syncwarp
    }
}

__global__ __launch_bounds__(1024)
void mg_reduce(float* __restrict__ ld, int B)
{
    int b = blockIdx.x * blockDim.x + threadIdx.x;
    if (b < B) {
        float s = 0.0f;
        #pragma unroll
        for (int g = 0; g < GROUPS; g++) s += g_partial[(size_t)g * B + b];
        ld[b] = s;
    }
}

extern "C" void kernel_launch(void* const* d_in, const int* in_sizes, int n_in,
                              void* d_out, int out_size)
{
    const float* x   = (const float*)d_in[0];
    const float* xv  = (const float*)d_in[1];
    const float* cdf = (const float*)d_in[2];
    float* out = (float*)d_out;

    const int B = in_sizes[0] / DIMS;

    static bool attr_set = false;
    if (!attr_set) {
        cudaFuncSetAttribute(mg_main, cudaFuncAttributeMaxDynamicSharedMemorySize, SMEM_TOTAL);
        attr_set = true;
    }

    dim3 grid(NCHUNK, GROUPS);
    int spb = (B + NCHUNK - 1) / NCHUNK;
    float* ld = out + (size_t)B * DIMS;

    mg_main<<<grid, TPB, SMEM_TOTAL>>>(x, xv, cdf, out, B, spb);
    mg_reduce<<<(B + 1023) / 1024, 1024>>>(ld, B);
}